// round 12
// baseline (speedup 1.0000x reference)
#include <cuda_runtime.h>
#include <stdint.h>

// TopK mask: out = x * (x in top-k of its row), ties -> lowest index.
// R12: single kernel, 8 CTAs/SM. Hot path reads the row ONCE: pass1
// compacts (value, col) candidate pairs into smem, rank-scan finds the
// K-th value, epilogue zero-fills the output row (no loads) and scatters
// the <=K kept values from smem. Cold path (wrong distribution / tie
// straddle) = exact streaming key-domain radix select, unchanged from R11.

#define F_DIM 4096
#define TPB   256
#define CAP   192   // candidate capacity; count(x>=2.0) ~ 93 +- 9.5 for N(0,1)

static __device__ __forceinline__ unsigned f2key(unsigned u) {
    return u ^ ((unsigned)((int)u >> 31) | 0x80000000u);
}

__global__ __launch_bounds__(TPB, 8)
void topk_mask_kernel(const float* __restrict__ x,
                      const int*   __restrict__ kptr,
                      int kfallback,
                      float* __restrict__ out)
{
    const int tid  = threadIdx.x;
    const int lane = tid & 31;
    const int wid  = tid >> 5;
    const size_t row = blockIdx.x;

    __shared__ __align__(16) float s_cand[CAP + 2];   // cold path reuses as keys
    __shared__ unsigned short    s_col[CAP];
    __shared__ unsigned s_wcnt[8];
    __shared__ unsigned s_warp[8][4];
    __shared__ unsigned s_ctrl[8];  // [0]=Kstar [1]=winner cnt [2]=c_ge [3]=c_gt [7]=cand ctr

    const float4* __restrict__ xr   = reinterpret_cast<const float4*>(x) + row * (F_DIM / 4);
    float4*       __restrict__ orow = reinterpret_cast<float4*>(out)     + row * (F_DIM / 4);
    float*        __restrict__ orف  = nullptr; (void)orف;
    float*        __restrict__ orowf = reinterpret_cast<float*>(out) + row * F_DIM;

    const int kv = (kptr != nullptr) ? __ldg(kptr) : kfallback;

    if (kv <= 0) {
        float4 z; z.x = z.y = z.z = z.w = 0.0f;
        #pragma unroll
        for (int i = 0; i < 4; ++i) orow[tid + i * 256] = z;
        return;
    }
    if (kv >= F_DIM) {
        #pragma unroll
        for (int i = 0; i < 4; ++i) orow[tid + i * 256] = __ldg(xr + tid + i * 256);
        return;
    }
    const unsigned K = (unsigned)kv;
    const float T = 2.0f;

    bool fallback = false;

    // ========== PASS 1: count + compact (value, col) pairs >= T ==========
    unsigned n_c;
    {
        float4 a0 = __ldg(xr + tid);
        float4 a1 = __ldg(xr + tid + 256);
        float4 a2 = __ldg(xr + tid + 512);
        float4 a3 = __ldg(xr + tid + 768);

        unsigned cnt = 0;
        cnt += (a0.x >= T); cnt += (a0.y >= T); cnt += (a0.z >= T); cnt += (a0.w >= T);
        cnt += (a1.x >= T); cnt += (a1.y >= T); cnt += (a1.z >= T); cnt += (a1.w >= T);
        cnt += (a2.x >= T); cnt += (a2.y >= T); cnt += (a2.z >= T); cnt += (a2.w >= T);
        cnt += (a3.x >= T); cnt += (a3.y >= T); cnt += (a3.z >= T); cnt += (a3.w >= T);

        unsigned incl = cnt;
        #pragma unroll
        for (int d = 1; d < 32; d <<= 1) {
            unsigned nb = __shfl_up_sync(0xffffffffu, incl, d);
            if (lane >= d) incl += nb;
        }
        if (lane == 31) s_wcnt[wid] = incl;
        if (tid == 0)   s_ctrl[1] = 0u;
        __syncthreads();

        unsigned base = 0, tot = 0;
        #pragma unroll
        for (int w = 0; w < 8; ++w) {
            unsigned t = s_wcnt[w];
            tot += t;
            if (w < wid) base += t;
        }
        n_c = tot;
        if (n_c < K || n_c > CAP) {
            fallback = true;                       // uniform across block
        } else {
            unsigned pos = base + (incl - cnt);
            const unsigned c0 = (unsigned)(tid << 2);
            if (a0.x >= T) { s_cand[pos] = a0.x; s_col[pos] = (unsigned short)(c0 + 0u);        ++pos; }
            if (a0.y >= T) { s_cand[pos] = a0.y; s_col[pos] = (unsigned short)(c0 + 1u);        ++pos; }
            if (a0.z >= T) { s_cand[pos] = a0.z; s_col[pos] = (unsigned short)(c0 + 2u);        ++pos; }
            if (a0.w >= T) { s_cand[pos] = a0.w; s_col[pos] = (unsigned short)(c0 + 3u);        ++pos; }
            if (a1.x >= T) { s_cand[pos] = a1.x; s_col[pos] = (unsigned short)(c0 + 1024u);     ++pos; }
            if (a1.y >= T) { s_cand[pos] = a1.y; s_col[pos] = (unsigned short)(c0 + 1025u);     ++pos; }
            if (a1.z >= T) { s_cand[pos] = a1.z; s_col[pos] = (unsigned short)(c0 + 1026u);     ++pos; }
            if (a1.w >= T) { s_cand[pos] = a1.w; s_col[pos] = (unsigned short)(c0 + 1027u);     ++pos; }
            if (a2.x >= T) { s_cand[pos] = a2.x; s_col[pos] = (unsigned short)(c0 + 2048u);     ++pos; }
            if (a2.y >= T) { s_cand[pos] = a2.y; s_col[pos] = (unsigned short)(c0 + 2049u);     ++pos; }
            if (a2.z >= T) { s_cand[pos] = a2.z; s_col[pos] = (unsigned short)(c0 + 2050u);     ++pos; }
            if (a2.w >= T) { s_cand[pos] = a2.w; s_col[pos] = (unsigned short)(c0 + 2051u);     ++pos; }
            if (a3.x >= T) { s_cand[pos] = a3.x; s_col[pos] = (unsigned short)(c0 + 3072u);     ++pos; }
            if (a3.y >= T) { s_cand[pos] = a3.y; s_col[pos] = (unsigned short)(c0 + 3073u);     ++pos; }
            if (a3.z >= T) { s_cand[pos] = a3.z; s_col[pos] = (unsigned short)(c0 + 3074u);     ++pos; }
            if (a3.w >= T) { s_cand[pos] = a3.w; s_col[pos] = (unsigned short)(c0 + 3075u);     ++pos; }
            if (tid == 0) {                        // pad for float2 pair loads
                s_cand[n_c]     = __int_as_float(0xff800000);
                s_cand[n_c + 1] = __int_as_float(0xff800000);
            }
        }
    }

    if (!fallback) {
        __syncthreads();
        // ---- gt-only rank scan: winner has exactly K-1 above it ----
        if ((unsigned)tid < n_c) {
            float c = s_cand[tid];
            unsigned gt = 0;
            const float2* p2 = reinterpret_cast<const float2*>(s_cand);
            const unsigned np = (n_c + 1u) >> 1;
            #pragma unroll 4
            for (unsigned jp = 0; jp < np; ++jp) {
                float2 w2 = p2[jp];
                gt += (w2.x > c);
                gt += (w2.y > c);
            }
            if (gt == K - 1u) {
                atomicAdd(&s_ctrl[1], 1u);
                s_ctrl[0] = __float_as_uint(c);    // duplicates: identical bits
            }
        }
        __syncthreads();

        const unsigned m = s_ctrl[1];
        if (m >= 1u) {
            const float Ks = __uint_as_float(s_ctrl[0]);
            unsigned Ccut = 0xFFFFFFFFu;
            if (m > 1u) {
                // budget = 1 equal element -> keep lowest col among == Ks
                unsigned mc = 0xFFFFFFFFu;
                if ((unsigned)tid < n_c && s_cand[tid] == Ks) mc = (unsigned)s_col[tid];
                mc = __reduce_min_sync(0xffffffffu, mc);
                if (lane == 0) s_wcnt[wid] = mc;
                __syncthreads();
                #pragma unroll
                for (int w = 0; w < 8; ++w) Ccut = min(Ccut, s_wcnt[w]);
            }

            // ---- zero-fill (no loads), then scatter survivors from smem ----
            {
                float4 z; z.x = z.y = z.z = z.w = 0.0f;
                #pragma unroll
                for (int i = 0; i < 4; ++i) orow[tid + i * 256] = z;
            }
            __syncthreads();   // order zero-fill before scatter (same CTA)
            if ((unsigned)tid < n_c) {
                float    v = s_cand[tid];
                unsigned c = (unsigned)s_col[tid];
                bool keep = (v > Ks) || (v == Ks && c <= Ccut);
                if (keep) orowf[c] = v;
            }
            return;
        }
        // m == 0: tie group straddles K -> cold path
    }

    // ============== COLD PATH: exact key-domain radix select =============
    // Streaming row reads (one float4 at a time) keep register pressure at
    // the hot path's level. Rare for the reference distribution.
    __syncthreads();
    unsigned* s_ckey = reinterpret_cast<unsigned*>(s_cand);
    const uint4* __restrict__ xu = reinterpret_cast<const uint4*>(x) + row * (F_DIM / 4);

    unsigned lo = 0u, cnt_lo = F_DIM, cnt_hi1 = 0u;
    int shift = 32;

    #pragma unroll 1
    while (cnt_lo - cnt_hi1 > CAP && shift > 0) {
        unsigned q = 1u << (shift - 2);
        unsigned t1 = lo + q, t2 = lo + 2u * q, t3 = lo + 3u * q;
        unsigned c1 = 0, c2 = 0, c3 = 0;
        #pragma unroll 1
        for (int i = 0; i < 4; ++i) {
            uint4 b = __ldg(xu + tid + i * 256);
            unsigned k;
            k = f2key(b.x); c1 += (k >= t1); c2 += (k >= t2); c3 += (k >= t3);
            k = f2key(b.y); c1 += (k >= t1); c2 += (k >= t2); c3 += (k >= t3);
            k = f2key(b.z); c1 += (k >= t1); c2 += (k >= t2); c3 += (k >= t3);
            k = f2key(b.w); c1 += (k >= t1); c2 += (k >= t2); c3 += (k >= t3);
        }
        c1 = __reduce_add_sync(0xffffffffu, c1);
        c2 = __reduce_add_sync(0xffffffffu, c2);
        c3 = __reduce_add_sync(0xffffffffu, c3);
        if (lane == 0) { s_warp[wid][0] = c1; s_warp[wid][1] = c2; s_warp[wid][2] = c3; }
        __syncthreads();
        unsigned C1 = 0, C2 = 0, C3 = 0;
        #pragma unroll
        for (int w = 0; w < 8; ++w) { C1 += s_warp[w][0]; C2 += s_warp[w][1]; C3 += s_warp[w][2]; }
        __syncthreads();
        if      (C3 >= K) { lo = t3; cnt_lo = C3; }
        else if (C2 >= K) { lo = t2; cnt_lo = C2; cnt_hi1 = C3; }
        else if (C1 >= K) { lo = t1; cnt_lo = C1; cnt_hi1 = C2; }
        else              {                      cnt_hi1 = C1; }
        shift -= 2;
    }

    unsigned Kstar, c_ge, c_gt;
    if (shift == 0) {
        Kstar = lo; c_ge = cnt_lo; c_gt = cnt_hi1;
    } else {
        if (tid == 0) s_ctrl[7] = 0u;
        __syncthreads();
        const unsigned hib = lo + ((1u << shift) - 1u);
        #pragma unroll 1
        for (int i = 0; i < 4; ++i) {
            uint4 b = __ldg(xu + tid + i * 256);
            #pragma unroll
            for (int j = 0; j < 4; ++j) {
                unsigned k = f2key(j == 0 ? b.x : j == 1 ? b.y : j == 2 ? b.z : b.w);
                bool in = (k >= lo) && (k <= hib);
                unsigned mk = __ballot_sync(0xffffffffu, in);
                unsigned base = 0u;
                if (lane == 0) base = atomicAdd(&s_ctrl[7], (unsigned)__popc(mk));
                base = __shfl_sync(0xffffffffu, base, 0);
                if (in) {
                    unsigned p = base + (unsigned)__popc(mk & ((1u << lane) - 1u));
                    if (p < CAP) s_ckey[p] = k;
                }
            }
        }
        __syncthreads();

        const unsigned nc = s_ctrl[7];
        const unsigned A  = cnt_hi1;
        if ((unsigned)tid < nc) {
            unsigned ck = s_ckey[tid];
            unsigned gt = 0, ge = 0;
            #pragma unroll 4
            for (unsigned j = 0; j < nc; ++j) {
                unsigned vv = s_ckey[j];
                gt += (vv >  ck);
                ge += (vv >= ck);
            }
            unsigned GT = A + gt, GE = A + ge;
            if (GT < K && GE >= K) { s_ctrl[0] = ck; s_ctrl[2] = GE; s_ctrl[3] = GT; }
        }
        __syncthreads();
        Kstar = s_ctrl[0]; c_ge = s_ctrl[2]; c_gt = s_ctrl[3];
    }

    unsigned Ccut = 0xFFFFFFFFu;
    {
        unsigned budget = K - c_gt;
        unsigned c_eq   = c_ge - c_gt;
        if (budget < c_eq) {
            int loB = 0, hiB = F_DIM - 1;
            #pragma unroll 1
            while (loB < hiB) {
                int mid = (loB + hiB) >> 1;
                unsigned cc = 0;
                #pragma unroll 1
                for (int i = 0; i < 4; ++i) {
                    uint4 b = __ldg(xu + tid + i * 256);
                    unsigned col0 = (unsigned)((i << 10) + (tid << 2));
                    cc += (f2key(b.x) == Kstar && (int)(col0 + 0u) <= mid) ? 1u : 0u;
                    cc += (f2key(b.y) == Kstar && (int)(col0 + 1u) <= mid) ? 1u : 0u;
                    cc += (f2key(b.z) == Kstar && (int)(col0 + 2u) <= mid) ? 1u : 0u;
                    cc += (f2key(b.w) == Kstar && (int)(col0 + 3u) <= mid) ? 1u : 0u;
                }
                cc = __reduce_add_sync(0xffffffffu, cc);
                if (lane == 0) s_warp[wid][0] = cc;
                __syncthreads();
                unsigned Ct = 0;
                #pragma unroll
                for (int w = 0; w < 8; ++w) Ct += s_warp[w][0];
                __syncthreads();
                if (Ct >= budget) hiB = mid; else loB = mid + 1;
            }
            Ccut = (unsigned)loB;
        }
    }

    #pragma unroll 1
    for (int i = 0; i < 4; ++i) {
        uint4 b = __ldg(xu + tid + i * 256);
        unsigned col0 = (unsigned)((i << 10) + (tid << 2));
        unsigned k0 = f2key(b.x), k1 = f2key(b.y), k2 = f2key(b.z), k3 = f2key(b.w);
        uint4 o;
        o.x = ((k0 > Kstar) || (k0 == Kstar && (col0 + 0u) <= Ccut)) ? b.x : 0u;
        o.y = ((k1 > Kstar) || (k1 == Kstar && (col0 + 1u) <= Ccut)) ? b.y : 0u;
        o.z = ((k2 > Kstar) || (k2 == Kstar && (col0 + 2u) <= Ccut)) ? b.z : 0u;
        o.w = ((k3 > Kstar) || (k3 == Kstar && (col0 + 3u) <= Ccut)) ? b.w : 0u;
        reinterpret_cast<uint4*>(orow)[tid + i * 256] = o;
    }
}

extern "C" void kernel_launch(void* const* d_in, const int* in_sizes, int n_in,
                              void* d_out, int out_size)
{
    const float* x  = (const float*)d_in[0];
    const int*   kp = (n_in >= 2) ? (const int*)d_in[1] : nullptr;
    float* out = (float*)d_out;

    int B = in_sizes[0] / F_DIM;
    topk_mask_kernel<<<B, TPB>>>(x, kp, 64, out);
}

// round 13
// speedup vs baseline: 1.0563x; 1.0563x over previous
#include <cuda_runtime.h>
#include <stdint.h>

// TopK mask: out = x * (x in top-k of its row), ties -> lowest index.
// R13 = R11 (best: 88.2us) + micro-cuts:
//   - rank scan reads candidates via float4 LDS (pad to x4 with -inf)
//   - pass1 cross-warp reduction reads s_wcnt as 2x uint4
//   - output stores use __stcs (write-once data, evict-first: keep L2 for x)
// Hot path: fixed threshold 2.0f, float-domain rank select, masked write.
// Cold path: exact streaming key-domain radix select (unchanged).

#define F_DIM 4096
#define TPB   256
#define CAP   192   // candidate capacity; count(x>=2.0) ~ 93 +- 9.5 for N(0,1)

static __device__ __forceinline__ unsigned f2key(unsigned u) {
    return u ^ ((unsigned)((int)u >> 31) | 0x80000000u);
}

static __device__ __forceinline__ void st_cs4(float4* p, float4 v) {
    __stcs(p, v);
}

__global__ __launch_bounds__(TPB, 8)
void topk_mask_kernel(const float* __restrict__ x,
                      const int*   __restrict__ kptr,
                      int kfallback,
                      float* __restrict__ out)
{
    const int tid  = threadIdx.x;
    const int lane = tid & 31;
    const int wid  = tid >> 5;
    const size_t row = blockIdx.x;

    __shared__ __align__(16) float s_cand[CAP + 4];   // cold path reuses as keys
    __shared__ __align__(16) unsigned s_wcnt[8];
    __shared__ unsigned s_warp[8][4];
    __shared__ unsigned s_ctrl[8];  // [0]=Kstar [1]=winner cnt [2]=c_ge [3]=c_gt [7]=cand ctr

    const float4* __restrict__ xr   = reinterpret_cast<const float4*>(x) + row * (F_DIM / 4);
    float4*       __restrict__ orow = reinterpret_cast<float4*>(out)     + row * (F_DIM / 4);

    const int kv = (kptr != nullptr) ? __ldg(kptr) : kfallback;

    if (kv <= 0) {
        float4 z; z.x = z.y = z.z = z.w = 0.0f;
        #pragma unroll
        for (int i = 0; i < 4; ++i) st_cs4(&orow[tid + i * 256], z);
        return;
    }
    if (kv >= F_DIM) {
        #pragma unroll
        for (int i = 0; i < 4; ++i) st_cs4(&orow[tid + i * 256], __ldg(xr + tid + i * 256));
        return;
    }
    const unsigned K = (unsigned)kv;
    const float T = 2.0f;

    bool fallback = false;

    // ================== HOT PATH: fixed threshold 2.0f ==================
    unsigned n_c;
    {
        float4 a0 = __ldg(xr + tid);
        float4 a1 = __ldg(xr + tid + 256);
        float4 a2 = __ldg(xr + tid + 512);
        float4 a3 = __ldg(xr + tid + 768);

        unsigned cnt = 0;
        cnt += (a0.x >= T); cnt += (a0.y >= T); cnt += (a0.z >= T); cnt += (a0.w >= T);
        cnt += (a1.x >= T); cnt += (a1.y >= T); cnt += (a1.z >= T); cnt += (a1.w >= T);
        cnt += (a2.x >= T); cnt += (a2.y >= T); cnt += (a2.z >= T); cnt += (a2.w >= T);
        cnt += (a3.x >= T); cnt += (a3.y >= T); cnt += (a3.z >= T); cnt += (a3.w >= T);

        unsigned incl = cnt;
        #pragma unroll
        for (int d = 1; d < 32; d <<= 1) {
            unsigned nb = __shfl_up_sync(0xffffffffu, incl, d);
            if (lane >= d) incl += nb;
        }
        if (lane == 31) s_wcnt[wid] = incl;
        if (tid == 0)   s_ctrl[1] = 0u;
        __syncthreads();

        // vectorized cross-warp reduction: 2x LDS.128
        uint4 w0 = reinterpret_cast<const uint4*>(s_wcnt)[0];
        uint4 w1 = reinterpret_cast<const uint4*>(s_wcnt)[1];
        unsigned wv[8] = { w0.x, w0.y, w0.z, w0.w, w1.x, w1.y, w1.z, w1.w };
        unsigned base = 0, tot = 0;
        #pragma unroll
        for (int w = 0; w < 8; ++w) {
            tot += wv[w];
            if (w < wid) base += wv[w];
        }
        n_c = tot;
        if (n_c < K || n_c > CAP) {
            fallback = true;                       // uniform across block
        } else {
            unsigned pos = base + (incl - cnt);
            if (a0.x >= T) s_cand[pos++] = a0.x;
            if (a0.y >= T) s_cand[pos++] = a0.y;
            if (a0.z >= T) s_cand[pos++] = a0.z;
            if (a0.w >= T) s_cand[pos++] = a0.w;
            if (a1.x >= T) s_cand[pos++] = a1.x;
            if (a1.y >= T) s_cand[pos++] = a1.y;
            if (a1.z >= T) s_cand[pos++] = a1.z;
            if (a1.w >= T) s_cand[pos++] = a1.w;
            if (a2.x >= T) s_cand[pos++] = a2.x;
            if (a2.y >= T) s_cand[pos++] = a2.y;
            if (a2.z >= T) s_cand[pos++] = a2.z;
            if (a2.w >= T) s_cand[pos++] = a2.w;
            if (a3.x >= T) s_cand[pos++] = a3.x;
            if (a3.y >= T) s_cand[pos++] = a3.y;
            if (a3.z >= T) s_cand[pos++] = a3.z;
            if (a3.w >= T) s_cand[pos++] = a3.w;
            if (tid == 0) {                        // pad to multiple of 4 for float4 loads
                s_cand[n_c]     = __int_as_float(0xff800000);
                s_cand[n_c + 1] = __int_as_float(0xff800000);
                s_cand[n_c + 2] = __int_as_float(0xff800000);
                s_cand[n_c + 3] = __int_as_float(0xff800000);
            }
        }
    }

    if (!fallback) {
        __syncthreads();
        // ---- gt-only rank scan (float4 LDS): winner has K-1 above it ----
        if ((unsigned)tid < n_c) {
            float c = s_cand[tid];
            unsigned gt = 0;
            const float4* p4 = reinterpret_cast<const float4*>(s_cand);
            const unsigned np = (n_c + 3u) >> 2;
            #pragma unroll 4
            for (unsigned jp = 0; jp < np; ++jp) {
                float4 w4 = p4[jp];
                gt += (w4.x > c);
                gt += (w4.y > c);
                gt += (w4.z > c);
                gt += (w4.w > c);
            }
            if (gt == K - 1u) {
                atomicAdd(&s_ctrl[1], 1u);
                s_ctrl[0] = __float_as_uint(c);    // duplicates: identical bits
            }
        }
        __syncthreads();

        const unsigned m = s_ctrl[1];
        if (m >= 1u) {
            const float Ks = __uint_as_float(s_ctrl[0]);
            if (m == 1u) {
                // common case: keep iff v >= Ks
                #pragma unroll
                for (int i = 0; i < 4; ++i) {
                    float4 v4 = __ldg(xr + tid + i * 256);
                    float4 o;
                    o.x = (v4.x >= Ks) ? v4.x : 0.0f;
                    o.y = (v4.y >= Ks) ? v4.y : 0.0f;
                    o.z = (v4.z >= Ks) ? v4.z : 0.0f;
                    o.w = (v4.w >= Ks) ? v4.w : 0.0f;
                    st_cs4(&orow[tid + i * 256], o);
                }
                return;
            }
            // m > 1: budget is exactly 1 equal element -> lowest-index == Ks
            unsigned mc = 0xFFFFFFFFu;
            #pragma unroll
            for (int i = 0; i < 4; ++i) {
                float4 v4 = __ldg(xr + tid + i * 256);
                unsigned col0 = (unsigned)((i << 10) + (tid << 2));
                if (v4.x == Ks) mc = min(mc, col0 + 0u);
                if (v4.y == Ks) mc = min(mc, col0 + 1u);
                if (v4.z == Ks) mc = min(mc, col0 + 2u);
                if (v4.w == Ks) mc = min(mc, col0 + 3u);
            }
            mc = __reduce_min_sync(0xffffffffu, mc);
            if (lane == 0) s_wcnt[wid] = mc;
            __syncthreads();
            unsigned Ccut = 0xFFFFFFFFu;
            #pragma unroll
            for (int w = 0; w < 8; ++w) Ccut = min(Ccut, s_wcnt[w]);

            #pragma unroll
            for (int i = 0; i < 4; ++i) {
                float4 v4 = __ldg(xr + tid + i * 256);
                unsigned col0 = (unsigned)((i << 10) + (tid << 2));
                float4 o;
                o.x = ((v4.x > Ks) || (v4.x == Ks && (col0 + 0u) <= Ccut)) ? v4.x : 0.0f;
                o.y = ((v4.y > Ks) || (v4.y == Ks && (col0 + 1u) <= Ccut)) ? v4.y : 0.0f;
                o.z = ((v4.z > Ks) || (v4.z == Ks && (col0 + 2u) <= Ccut)) ? v4.z : 0.0f;
                o.w = ((v4.w > Ks) || (v4.w == Ks && (col0 + 3u) <= Ccut)) ? v4.w : 0.0f;
                st_cs4(&orow[tid + i * 256], o);
            }
            return;
        }
        // m == 0: tie group straddles K -> cold path
    }

    // ============== COLD PATH: exact key-domain radix select =============
    // Streaming row reads keep register pressure at the hot path's level.
    __syncthreads();
    unsigned* s_ckey = reinterpret_cast<unsigned*>(s_cand);
    const uint4* __restrict__ xu = reinterpret_cast<const uint4*>(x) + row * (F_DIM / 4);

    unsigned lo = 0u, cnt_lo = F_DIM, cnt_hi1 = 0u;
    int shift = 32;

    #pragma unroll 1
    while (cnt_lo - cnt_hi1 > CAP && shift > 0) {
        unsigned q = 1u << (shift - 2);
        unsigned t1 = lo + q, t2 = lo + 2u * q, t3 = lo + 3u * q;
        unsigned c1 = 0, c2 = 0, c3 = 0;
        #pragma unroll 1
        for (int i = 0; i < 4; ++i) {
            uint4 b = __ldg(xu + tid + i * 256);
            unsigned k;
            k = f2key(b.x); c1 += (k >= t1); c2 += (k >= t2); c3 += (k >= t3);
            k = f2key(b.y); c1 += (k >= t1); c2 += (k >= t2); c3 += (k >= t3);
            k = f2key(b.z); c1 += (k >= t1); c2 += (k >= t2); c3 += (k >= t3);
            k = f2key(b.w); c1 += (k >= t1); c2 += (k >= t2); c3 += (k >= t3);
        }
        c1 = __reduce_add_sync(0xffffffffu, c1);
        c2 = __reduce_add_sync(0xffffffffu, c2);
        c3 = __reduce_add_sync(0xffffffffu, c3);
        if (lane == 0) { s_warp[wid][0] = c1; s_warp[wid][1] = c2; s_warp[wid][2] = c3; }
        __syncthreads();
        unsigned C1 = 0, C2 = 0, C3 = 0;
        #pragma unroll
        for (int w = 0; w < 8; ++w) { C1 += s_warp[w][0]; C2 += s_warp[w][1]; C3 += s_warp[w][2]; }
        __syncthreads();
        if      (C3 >= K) { lo = t3; cnt_lo = C3; }
        else if (C2 >= K) { lo = t2; cnt_lo = C2; cnt_hi1 = C3; }
        else if (C1 >= K) { lo = t1; cnt_lo = C1; cnt_hi1 = C2; }
        else              {                      cnt_hi1 = C1; }
        shift -= 2;
    }

    unsigned Kstar, c_ge, c_gt;
    if (shift == 0) {
        Kstar = lo; c_ge = cnt_lo; c_gt = cnt_hi1;
    } else {
        if (tid == 0) s_ctrl[7] = 0u;
        __syncthreads();
        const unsigned hib = lo + ((1u << shift) - 1u);
        #pragma unroll 1
        for (int i = 0; i < 4; ++i) {
            uint4 b = __ldg(xu + tid + i * 256);
            #pragma unroll
            for (int j = 0; j < 4; ++j) {
                unsigned k = f2key(j == 0 ? b.x : j == 1 ? b.y : j == 2 ? b.z : b.w);
                bool in = (k >= lo) && (k <= hib);
                unsigned mk = __ballot_sync(0xffffffffu, in);
                unsigned base = 0u;
                if (lane == 0) base = atomicAdd(&s_ctrl[7], (unsigned)__popc(mk));
                base = __shfl_sync(0xffffffffu, base, 0);
                if (in) {
                    unsigned p = base + (unsigned)__popc(mk & ((1u << lane) - 1u));
                    if (p < CAP) s_ckey[p] = k;
                }
            }
        }
        __syncthreads();

        const unsigned nc = s_ctrl[7];
        const unsigned A  = cnt_hi1;
        if ((unsigned)tid < nc) {
            unsigned ck = s_ckey[tid];
            unsigned gt = 0, ge = 0;
            #pragma unroll 4
            for (unsigned j = 0; j < nc; ++j) {
                unsigned vv = s_ckey[j];
                gt += (vv >  ck);
                ge += (vv >= ck);
            }
            unsigned GT = A + gt, GE = A + ge;
            if (GT < K && GE >= K) { s_ctrl[0] = ck; s_ctrl[2] = GE; s_ctrl[3] = GT; }
        }
        __syncthreads();
        Kstar = s_ctrl[0]; c_ge = s_ctrl[2]; c_gt = s_ctrl[3];
    }

    unsigned Ccut = 0xFFFFFFFFu;
    {
        unsigned budget = K - c_gt;
        unsigned c_eq   = c_ge - c_gt;
        if (budget < c_eq) {
            int loB = 0, hiB = F_DIM - 1;
            #pragma unroll 1
            while (loB < hiB) {
                int mid = (loB + hiB) >> 1;
                unsigned cc = 0;
                #pragma unroll 1
                for (int i = 0; i < 4; ++i) {
                    uint4 b = __ldg(xu + tid + i * 256);
                    unsigned col0 = (unsigned)((i << 10) + (tid << 2));
                    cc += (f2key(b.x) == Kstar && (int)(col0 + 0u) <= mid) ? 1u : 0u;
                    cc += (f2key(b.y) == Kstar && (int)(col0 + 1u) <= mid) ? 1u : 0u;
                    cc += (f2key(b.z) == Kstar && (int)(col0 + 2u) <= mid) ? 1u : 0u;
                    cc += (f2key(b.w) == Kstar && (int)(col0 + 3u) <= mid) ? 1u : 0u;
                }
                cc = __reduce_add_sync(0xffffffffu, cc);
                if (lane == 0) s_warp[wid][0] = cc;
                __syncthreads();
                unsigned Ct = 0;
                #pragma unroll
                for (int w = 0; w < 8; ++w) Ct += s_warp[w][0];
                __syncthreads();
                if (Ct >= budget) hiB = mid; else loB = mid + 1;
            }
            Ccut = (unsigned)loB;
        }
    }

    #pragma unroll 1
    for (int i = 0; i < 4; ++i) {
        uint4 b = __ldg(xu + tid + i * 256);
        unsigned col0 = (unsigned)((i << 10) + (tid << 2));
        unsigned k0 = f2key(b.x), k1 = f2key(b.y), k2 = f2key(b.z), k3 = f2key(b.w);
        uint4 o;
        o.x = ((k0 > Kstar) || (k0 == Kstar && (col0 + 0u) <= Ccut)) ? b.x : 0u;
        o.y = ((k1 > Kstar) || (k1 == Kstar && (col0 + 1u) <= Ccut)) ? b.y : 0u;
        o.z = ((k2 > Kstar) || (k2 == Kstar && (col0 + 2u) <= Ccut)) ? b.z : 0u;
        o.w = ((k3 > Kstar) || (k3 == Kstar && (col0 + 3u) <= Ccut)) ? b.w : 0u;
        __stcs(&reinterpret_cast<uint4*>(orow)[tid + i * 256], o);
    }
}

extern "C" void kernel_launch(void* const* d_in, const int* in_sizes, int n_in,
                              void* d_out, int out_size)
{
    const float* x  = (const float*)d_in[0];
    const int*   kp = (n_in >= 2) ? (const int*)d_in[1] : nullptr;
    float* out = (float*)d_out;

    int B = in_sizes[0] / F_DIM;
    topk_mask_kernel<<<B, TPB>>>(x, kp, 64, out);
}

// round 15
// speedup vs baseline: 1.0953x; 1.0369x over previous
#include <cuda_runtime.h>
#include <stdint.h>

// TopK mask: out = x * (x in top-k of its row), ties -> lowest index.
// R14 = R13 + keep the row in registers across the rank scan: the write
// phase is pure FSEL+STG (no second row read). Cold path stays streaming
// so hot-path register ceiling (32 @ 8 CTAs/SM) is preserved.

#define F_DIM 4096
#define TPB   256
#define CAP   192   // candidate capacity; count(x>=2.0) ~ 93 +- 9.5 for N(0,1)

static __device__ __forceinline__ unsigned f2key(unsigned u) {
    return u ^ ((unsigned)((int)u >> 31) | 0x80000000u);
}

__global__ __launch_bounds__(TPB, 8)
void topk_mask_kernel(const float* __restrict__ x,
                      const int*   __restrict__ kptr,
                      int kfallback,
                      float* __restrict__ out)
{
    const int tid  = threadIdx.x;
    const int lane = tid & 31;
    const int wid  = tid >> 5;
    const size_t row = blockIdx.x;

    __shared__ __align__(16) float s_cand[CAP + 4];   // cold path reuses as keys
    __shared__ __align__(16) unsigned s_wcnt[8];
    __shared__ unsigned s_warp[8][4];
    __shared__ unsigned s_ctrl[8];  // [0]=Kstar [1]=winner cnt [2]=c_ge [3]=c_gt [7]=cand ctr

    const float4* __restrict__ xr   = reinterpret_cast<const float4*>(x) + row * (F_DIM / 4);
    float4*       __restrict__ orow = reinterpret_cast<float4*>(out)     + row * (F_DIM / 4);

    const int kv = (kptr != nullptr) ? __ldg(kptr) : kfallback;

    if (kv <= 0) {
        float4 z; z.x = z.y = z.z = z.w = 0.0f;
        #pragma unroll
        for (int i = 0; i < 4; ++i) __stcs(&orow[tid + i * 256], z);
        return;
    }
    if (kv >= F_DIM) {
        #pragma unroll
        for (int i = 0; i < 4; ++i) __stcs(&orow[tid + i * 256], __ldg(xr + tid + i * 256));
        return;
    }
    const unsigned K = (unsigned)kv;
    const float T = 2.0f;

    bool fallback = false;

    // ================== HOT PATH: fixed threshold 2.0f ==================
    // Row stays in registers a0..a3 until the write.
    float4 a0 = __ldg(xr + tid);
    float4 a1 = __ldg(xr + tid + 256);
    float4 a2 = __ldg(xr + tid + 512);
    float4 a3 = __ldg(xr + tid + 768);

    unsigned n_c;
    {
        unsigned cnt = 0;
        cnt += (a0.x >= T); cnt += (a0.y >= T); cnt += (a0.z >= T); cnt += (a0.w >= T);
        cnt += (a1.x >= T); cnt += (a1.y >= T); cnt += (a1.z >= T); cnt += (a1.w >= T);
        cnt += (a2.x >= T); cnt += (a2.y >= T); cnt += (a2.z >= T); cnt += (a2.w >= T);
        cnt += (a3.x >= T); cnt += (a3.y >= T); cnt += (a3.z >= T); cnt += (a3.w >= T);

        unsigned incl = cnt;
        #pragma unroll
        for (int d = 1; d < 32; d <<= 1) {
            unsigned nb = __shfl_up_sync(0xffffffffu, incl, d);
            if (lane >= d) incl += nb;
        }
        if (lane == 31) s_wcnt[wid] = incl;
        if (tid == 0)   s_ctrl[1] = 0u;
        __syncthreads();

        uint4 w0 = reinterpret_cast<const uint4*>(s_wcnt)[0];
        uint4 w1 = reinterpret_cast<const uint4*>(s_wcnt)[1];
        unsigned wv[8] = { w0.x, w0.y, w0.z, w0.w, w1.x, w1.y, w1.z, w1.w };
        unsigned base = 0, tot = 0;
        #pragma unroll
        for (int w = 0; w < 8; ++w) {
            tot += wv[w];
            if (w < wid) base += wv[w];
        }
        n_c = tot;
        if (n_c < K || n_c > CAP) {
            fallback = true;                       // uniform across block
        } else {
            unsigned pos = base + (incl - cnt);
            if (a0.x >= T) s_cand[pos++] = a0.x;
            if (a0.y >= T) s_cand[pos++] = a0.y;
            if (a0.z >= T) s_cand[pos++] = a0.z;
            if (a0.w >= T) s_cand[pos++] = a0.w;
            if (a1.x >= T) s_cand[pos++] = a1.x;
            if (a1.y >= T) s_cand[pos++] = a1.y;
            if (a1.z >= T) s_cand[pos++] = a1.z;
            if (a1.w >= T) s_cand[pos++] = a1.w;
            if (a2.x >= T) s_cand[pos++] = a2.x;
            if (a2.y >= T) s_cand[pos++] = a2.y;
            if (a2.z >= T) s_cand[pos++] = a2.z;
            if (a2.w >= T) s_cand[pos++] = a2.w;
            if (a3.x >= T) s_cand[pos++] = a3.x;
            if (a3.y >= T) s_cand[pos++] = a3.y;
            if (a3.z >= T) s_cand[pos++] = a3.z;
            if (a3.w >= T) s_cand[pos++] = a3.w;
            if (tid == 0) {                        // pad to x4 for float4 loads
                s_cand[n_c]     = __int_as_float(0xff800000);
                s_cand[n_c + 1] = __int_as_float(0xff800000);
                s_cand[n_c + 2] = __int_as_float(0xff800000);
                s_cand[n_c + 3] = __int_as_float(0xff800000);
            }
        }
    }

    if (!fallback) {
        __syncthreads();
        // ---- gt-only rank scan (float4 LDS): winner has K-1 above it ----
        if ((unsigned)tid < n_c) {
            float c = s_cand[tid];
            unsigned gt = 0;
            const float4* p4 = reinterpret_cast<const float4*>(s_cand);
            const unsigned np = (n_c + 3u) >> 2;
            #pragma unroll 4
            for (unsigned jp = 0; jp < np; ++jp) {
                float4 w4 = p4[jp];
                gt += (w4.x > c);
                gt += (w4.y > c);
                gt += (w4.z > c);
                gt += (w4.w > c);
            }
            if (gt == K - 1u) {
                atomicAdd(&s_ctrl[1], 1u);
                s_ctrl[0] = __float_as_uint(c);    // duplicates: identical bits
            }
        }
        __syncthreads();

        const unsigned m = s_ctrl[1];
        if (m >= 1u) {
            const float Ks = __uint_as_float(s_ctrl[0]);
            if (m == 1u) {
                // common case: keep iff v >= Ks (registers -> stores, no loads)
                float4 o;
                o.x = (a0.x >= Ks) ? a0.x : 0.0f;
                o.y = (a0.y >= Ks) ? a0.y : 0.0f;
                o.z = (a0.z >= Ks) ? a0.z : 0.0f;
                o.w = (a0.w >= Ks) ? a0.w : 0.0f;
                __stcs(&orow[tid], o);
                o.x = (a1.x >= Ks) ? a1.x : 0.0f;
                o.y = (a1.y >= Ks) ? a1.y : 0.0f;
                o.z = (a1.z >= Ks) ? a1.z : 0.0f;
                o.w = (a1.w >= Ks) ? a1.w : 0.0f;
                __stcs(&orow[tid + 256], o);
                o.x = (a2.x >= Ks) ? a2.x : 0.0f;
                o.y = (a2.y >= Ks) ? a2.y : 0.0f;
                o.z = (a2.z >= Ks) ? a2.z : 0.0f;
                o.w = (a2.w >= Ks) ? a2.w : 0.0f;
                __stcs(&orow[tid + 512], o);
                o.x = (a3.x >= Ks) ? a3.x : 0.0f;
                o.y = (a3.y >= Ks) ? a3.y : 0.0f;
                o.z = (a3.z >= Ks) ? a3.z : 0.0f;
                o.w = (a3.w >= Ks) ? a3.w : 0.0f;
                __stcs(&orow[tid + 768], o);
                return;
            }
            // m > 1: budget is exactly 1 equal element -> lowest-index == Ks
            unsigned mc = 0xFFFFFFFFu;
            {
                const unsigned c0 = (unsigned)(tid << 2);
                if (a0.x == Ks) mc = min(mc, c0 + 0u);
                if (a0.y == Ks) mc = min(mc, c0 + 1u);
                if (a0.z == Ks) mc = min(mc, c0 + 2u);
                if (a0.w == Ks) mc = min(mc, c0 + 3u);
                if (a1.x == Ks) mc = min(mc, c0 + 1024u);
                if (a1.y == Ks) mc = min(mc, c0 + 1025u);
                if (a1.z == Ks) mc = min(mc, c0 + 1026u);
                if (a1.w == Ks) mc = min(mc, c0 + 1027u);
                if (a2.x == Ks) mc = min(mc, c0 + 2048u);
                if (a2.y == Ks) mc = min(mc, c0 + 2049u);
                if (a2.z == Ks) mc = min(mc, c0 + 2050u);
                if (a2.w == Ks) mc = min(mc, c0 + 2051u);
                if (a3.x == Ks) mc = min(mc, c0 + 3072u);
                if (a3.y == Ks) mc = min(mc, c0 + 3073u);
                if (a3.z == Ks) mc = min(mc, c0 + 3074u);
                if (a3.w == Ks) mc = min(mc, c0 + 3075u);
            }
            mc = __reduce_min_sync(0xffffffffu, mc);
            if (lane == 0) s_wcnt[wid] = mc;
            __syncthreads();
            unsigned Ccut = 0xFFFFFFFFu;
            #pragma unroll
            for (int w = 0; w < 8; ++w) Ccut = min(Ccut, s_wcnt[w]);

            {
                const unsigned c0 = (unsigned)(tid << 2);
                float4 o;
                o.x = ((a0.x > Ks) || (a0.x == Ks && (c0 + 0u)    <= Ccut)) ? a0.x : 0.0f;
                o.y = ((a0.y > Ks) || (a0.y == Ks && (c0 + 1u)    <= Ccut)) ? a0.y : 0.0f;
                o.z = ((a0.z > Ks) || (a0.z == Ks && (c0 + 2u)    <= Ccut)) ? a0.z : 0.0f;
                o.w = ((a0.w > Ks) || (a0.w == Ks && (c0 + 3u)    <= Ccut)) ? a0.w : 0.0f;
                __stcs(&orow[tid], o);
                o.x = ((a1.x > Ks) || (a1.x == Ks && (c0 + 1024u) <= Ccut)) ? a1.x : 0.0f;
                o.y = ((a1.y > Ks) || (a1.y == Ks && (c0 + 1025u) <= Ccut)) ? a1.y : 0.0f;
                o.z = ((a1.z > Ks) || (a1.z == Ks && (c0 + 1026u) <= Ccut)) ? a1.z : 0.0f;
                o.w = ((a1.w > Ks) || (a1.w == Ks && (c0 + 1027u) <= Ccut)) ? a1.w : 0.0f;
                __stcs(&orow[tid + 256], o);
                o.x = ((a2.x > Ks) || (a2.x == Ks && (c0 + 2048u) <= Ccut)) ? a2.x : 0.0f;
                o.y = ((a2.y > Ks) || (a2.y == Ks && (c0 + 2049u) <= Ccut)) ? a2.y : 0.0f;
                o.z = ((a2.z > Ks) || (a2.z == Ks && (c0 + 2050u) <= Ccut)) ? a2.z : 0.0f;
                o.w = ((a2.w > Ks) || (a2.w == Ks && (c0 + 2051u) <= Ccut)) ? a2.w : 0.0f;
                __stcs(&orow[tid + 512], o);
                o.x = ((a3.x > Ks) || (a3.x == Ks && (c0 + 3072u) <= Ccut)) ? a3.x : 0.0f;
                o.y = ((a3.y > Ks) || (a3.y == Ks && (c0 + 3073u) <= Ccut)) ? a3.y : 0.0f;
                o.z = ((a3.z > Ks) || (a3.z == Ks && (c0 + 3074u) <= Ccut)) ? a3.z : 0.0f;
                o.w = ((a3.w > Ks) || (a3.w == Ks && (c0 + 3075u) <= Ccut)) ? a3.w : 0.0f;
                __stcs(&orow[tid + 768], o);
            }
            return;
        }
        // m == 0: tie group straddles K -> cold path
    }

    // ============== COLD PATH: exact key-domain radix select =============
    // Streaming row reads keep register pressure at the hot path's level.
    __syncthreads();
    unsigned* s_ckey = reinterpret_cast<unsigned*>(s_cand);
    const uint4* __restrict__ xu = reinterpret_cast<const uint4*>(x) + row * (F_DIM / 4);

    unsigned lo = 0u, cnt_lo = F_DIM, cnt_hi1 = 0u;
    int shift = 32;

    #pragma unroll 1
    while (cnt_lo - cnt_hi1 > CAP && shift > 0) {
        unsigned q = 1u << (shift - 2);
        unsigned t1 = lo + q, t2 = lo + 2u * q, t3 = lo + 3u * q;
        unsigned c1 = 0, c2 = 0, c3 = 0;
        #pragma unroll 1
        for (int i = 0; i < 4; ++i) {
            uint4 b = __ldg(xu + tid + i * 256);
            unsigned k;
            k = f2key(b.x); c1 += (k >= t1); c2 += (k >= t2); c3 += (k >= t3);
            k = f2key(b.y); c1 += (k >= t1); c2 += (k >= t2); c3 += (k >= t3);
            k = f2key(b.z); c1 += (k >= t1); c2 += (k >= t2); c3 += (k >= t3);
            k = f2key(b.w); c1 += (k >= t1); c2 += (k >= t2); c3 += (k >= t3);
        }
        c1 = __reduce_add_sync(0xffffffffu, c1);
        c2 = __reduce_add_sync(0xffffffffu, c2);
        c3 = __reduce_add_sync(0xffffffffu, c3);
        if (lane == 0) { s_warp[wid][0] = c1; s_warp[wid][1] = c2; s_warp[wid][2] = c3; }
        __syncthreads();
        unsigned C1 = 0, C2 = 0, C3 = 0;
        #pragma unroll
        for (int w = 0; w < 8; ++w) { C1 += s_warp[w][0]; C2 += s_warp[w][1]; C3 += s_warp[w][2]; }
        __syncthreads();
        if      (C3 >= K) { lo = t3; cnt_lo = C3; }
        else if (C2 >= K) { lo = t2; cnt_lo = C2; cnt_hi1 = C3; }
        else if (C1 >= K) { lo = t1; cnt_lo = C1; cnt_hi1 = C2; }
        else              {                      cnt_hi1 = C1; }
        shift -= 2;
    }

    unsigned Kstar, c_ge, c_gt;
    if (shift == 0) {
        Kstar = lo; c_ge = cnt_lo; c_gt = cnt_hi1;
    } else {
        if (tid == 0) s_ctrl[7] = 0u;
        __syncthreads();
        const unsigned hib = lo + ((1u << shift) - 1u);
        #pragma unroll 1
        for (int i = 0; i < 4; ++i) {
            uint4 b = __ldg(xu + tid + i * 256);
            #pragma unroll
            for (int j = 0; j < 4; ++j) {
                unsigned k = f2key(j == 0 ? b.x : j == 1 ? b.y : j == 2 ? b.z : b.w);
                bool in = (k >= lo) && (k <= hib);
                unsigned mk = __ballot_sync(0xffffffffu, in);
                unsigned base = 0u;
                if (lane == 0) base = atomicAdd(&s_ctrl[7], (unsigned)__popc(mk));
                base = __shfl_sync(0xffffffffu, base, 0);
                if (in) {
                    unsigned p = base + (unsigned)__popc(mk & ((1u << lane) - 1u));
                    if (p < CAP) s_ckey[p] = k;
                }
            }
        }
        __syncthreads();

        const unsigned nc = s_ctrl[7];
        const unsigned A  = cnt_hi1;
        if ((unsigned)tid < nc) {
            unsigned ck = s_ckey[tid];
            unsigned gt = 0, ge = 0;
            #pragma unroll 4
            for (unsigned j = 0; j < nc; ++j) {
                unsigned vv = s_ckey[j];
                gt += (vv >  ck);
                ge += (vv >= ck);
            }
            unsigned GT = A + gt, GE = A + ge;
            if (GT < K && GE >= K) { s_ctrl[0] = ck; s_ctrl[2] = GE; s_ctrl[3] = GT; }
        }
        __syncthreads();
        Kstar = s_ctrl[0]; c_ge = s_ctrl[2]; c_gt = s_ctrl[3];
    }

    unsigned Ccut = 0xFFFFFFFFu;
    {
        unsigned budget = K - c_gt;
        unsigned c_eq   = c_ge - c_gt;
        if (budget < c_eq) {
            int loB = 0, hiB = F_DIM - 1;
            #pragma unroll 1
            while (loB < hiB) {
                int mid = (loB + hiB) >> 1;
                unsigned cc = 0;
                #pragma unroll 1
                for (int i = 0; i < 4; ++i) {
                    uint4 b = __ldg(xu + tid + i * 256);
                    unsigned col0 = (unsigned)((i << 10) + (tid << 2));
                    cc += (f2key(b.x) == Kstar && (int)(col0 + 0u) <= mid) ? 1u : 0u;
                    cc += (f2key(b.y) == Kstar && (int)(col0 + 1u) <= mid) ? 1u : 0u;
                    cc += (f2key(b.z) == Kstar && (int)(col0 + 2u) <= mid) ? 1u : 0u;
                    cc += (f2key(b.w) == Kstar && (int)(col0 + 3u) <= mid) ? 1u : 0u;
                }
                cc = __reduce_add_sync(0xffffffffu, cc);
                if (lane == 0) s_warp[wid][0] = cc;
                __syncthreads();
                unsigned Ct = 0;
                #pragma unroll
                for (int w = 0; w < 8; ++w) Ct += s_warp[w][0];
                __syncthreads();
                if (Ct >= budget) hiB = mid; else loB = mid + 1;
            }
            Ccut = (unsigned)loB;
        }
    }

    #pragma unroll 1
    for (int i = 0; i < 4; ++i) {
        uint4 b = __ldg(xu + tid + i * 256);
        unsigned col0 = (unsigned)((i << 10) + (tid << 2));
        unsigned k0 = f2key(b.x), k1 = f2key(b.y), k2 = f2key(b.z), k3 = f2key(b.w);
        uint4 o;
        o.x = ((k0 > Kstar) || (k0 == Kstar && (col0 + 0u) <= Ccut)) ? b.x : 0u;
        o.y = ((k1 > Kstar) || (k1 == Kstar && (col0 + 1u) <= Ccut)) ? b.y : 0u;
        o.z = ((k2 > Kstar) || (k2 == Kstar && (col0 + 2u) <= Ccut)) ? b.z : 0u;
        o.w = ((k3 > Kstar) || (k3 == Kstar && (col0 + 3u) <= Ccut)) ? b.w : 0u;
        __stcs(&reinterpret_cast<uint4*>(orow)[tid + i * 256], o);
    }
}

extern "C" void kernel_launch(void* const* d_in, const int* in_sizes, int n_in,
                              void* d_out, int out_size)
{
    const float* x  = (const float*)d_in[0];
    const int*   kp = (n_in >= 2) ? (const int*)d_in[1] : nullptr;
    float* out = (float*)d_out;

    int B = in_sizes[0] / F_DIM;
    topk_mask_kernel<<<B, TPB>>>(x, kp, 64, out);
}